// round 13
// baseline (speedup 1.0000x reference)
#include <cuda_runtime.h>
#include <math.h>

#define H_IMG 1440
#define W_IMG 1920
#define NPIX (H_IMG * W_IMG)
#define ZBLK 512

// ---------------- device scratch ----------------
__device__ float  g_warp0[NPIX];
__device__ float  g_warp1[NPIX];
__device__ double g_score  = 0.0;
__device__ double g_pixels = 0.0;
__device__ unsigned int g_ticket = 0u;

// ---------------- fp32 setup math ----------------
__device__ __forceinline__ void rodrigues_f(const float* v, float R[3][3]) {
    float x = v[0], y = v[1], z = v[2];
    float th = sqrtf(x * x + y * y + z * z) + 1e-12f;
    float kx = x / th, ky = y / th, kz = z / th;
    float s = sinf(th), c = cosf(th), C = 1.0f - c;
    R[0][0] = c + C * kx * kx;       R[0][1] = C * kx * ky - s * kz;  R[0][2] = C * kx * kz + s * ky;
    R[1][0] = C * ky * kx + s * kz;  R[1][1] = c + C * ky * ky;       R[1][2] = C * ky * kz - s * kx;
    R[2][0] = C * kz * kx - s * ky;  R[2][1] = C * kz * ky + s * kx;  R[2][2] = c + C * kz * kz;
}

__device__ void compute_setup(const float* __restrict__ focal,
                              const float* __restrict__ aa,
                              const float* __restrict__ centers,
                              float sM[2][9], float sb[2][3], float* sf) {
    float f = focal[0];
    const float k02 = 960.0f - 0.5f;
    const float k12 = 720.0f - 0.5f;
    float invf = 1.0f / f;
    float Ki[3][3] = {{invf, 0.0f, -k02 * invf}, {0.0f, invf, -k12 * invf}, {0.0f, 0.0f, 1.0f}};
    float K [3][3] = {{f, 0.0f, k02}, {0.0f, f, k12}, {0.0f, 0.0f, 1.0f}};

    float R[3][3][3];
    #pragma unroll
    for (int i = 0; i < 3; i++) rodrigues_f(aa + 3 * i, R[i]);

    float M1[3][3];
    #pragma unroll
    for (int i = 0; i < 3; i++)
        #pragma unroll
        for (int j = 0; j < 3; j++) {
            float s = 0.0f;
            #pragma unroll
            for (int k = 0; k < 3; k++) s += R[0][k][i] * Ki[k][j];
            M1[i][j] = s;
        }

    #pragma unroll
    for (int t = 0; t < 2; t++) {
        float A[3][3];
        #pragma unroll
        for (int i = 0; i < 3; i++)
            #pragma unroll
            for (int j = 0; j < 3; j++) {
                float s = 0.0f;
                #pragma unroll
                for (int k = 0; k < 3; k++) s += K[i][k] * R[t + 1][k][j];
                A[i][j] = s;
            }
        #pragma unroll
        for (int i = 0; i < 3; i++)
            #pragma unroll
            for (int j = 0; j < 3; j++) {
                float s = 0.0f;
                #pragma unroll
                for (int k = 0; k < 3; k++) s += A[i][k] * M1[k][j];
                sM[t][3 * i + j] = s;
            }
        float Cd[3] = {centers[0] - centers[3 * (t + 1) + 0],
                       centers[1] - centers[3 * (t + 1) + 1],
                       centers[2] - centers[3 * (t + 1) + 2]};
        #pragma unroll
        for (int i = 0; i < 3; i++) {
            float s = 0.0f;
            #pragma unroll
            for (int k = 0; k < 3; k++) s += A[i][k] * Cd[k];
            sb[t][i] = s;
        }
    }
    sf[0] = f;
    sf[1] = invf;
}

// ---------------- warp (both targets, 1-wide) ----------------
__device__ __forceinline__ float tapf(const float* __restrict__ img, float xi, float yi) {
    bool valid = (xi >= 0.0f) & (xi <= (float)(W_IMG - 1)) &
                 (yi >= 0.0f) & (yi <= (float)(H_IMG - 1));
    if (!valid) return 0.0f;
    int xc = (int)xi;
    int yc = (int)yi;
    return __ldg(img + (size_t)yc * W_IMG + xc);
}

__device__ __forceinline__ float warp_one(const float* __restrict__ img,
                                          const float* M, const float* b,
                                          float fx, float fy, float s) {
    float w0 = M[0] * fx + M[1] * fy + M[2] + b[0] * s;
    float w1 = M[3] * fx + M[4] * fy + M[5] + b[1] * s;
    float w2 = M[6] * fx + M[7] * fy + M[8] + b[2] * s;
    float iz = 1.0f / (w2 + 1e-8f);
    float px = w0 * iz, py = w1 * iz;
    float x0 = floorf(px), y0 = floorf(py);
    float wx = px - x0, wy = py - y0;
    float v00 = tapf(img, x0,        y0);
    float v10 = tapf(img, x0 + 1.0f, y0);
    float v01 = tapf(img, x0,        y0 + 1.0f);
    float v11 = tapf(img, x0 + 1.0f, y0 + 1.0f);
    return (1.0f - wy) * (1.0f - wx) * v00 + (1.0f - wy) * wx * v10 +
           wy * (1.0f - wx) * v01 + wy * wx * v11;
}

__global__ __launch_bounds__(256) void warp2_kernel(const float* __restrict__ depth,
                                                    const float* __restrict__ t0,
                                                    const float* __restrict__ t1,
                                                    const float* __restrict__ focal,
                                                    const float* __restrict__ aa,
                                                    const float* __restrict__ centers) {
    __shared__ float sM[2][9];
    __shared__ float sb[2][3];
    __shared__ float sf[2];
    if (threadIdx.x == 0) compute_setup(focal, aa, centers, sM, sb, sf);
    __syncthreads();

    int idx = blockIdx.x * blockDim.x + threadIdx.x;
    if (idx >= NPIX) return;
    int x = idx % W_IMG, y = idx / W_IMG;

    float d  = __ldg(depth + idx);
    float dl = (x > 0)          ? __ldg(depth + idx - 1)     : 0.0f;
    float dr = (x < W_IMG - 1)  ? __ldg(depth + idx + 1)     : 0.0f;
    float du = (y > 0)          ? __ldg(depth + idx - W_IMG) : 0.0f;
    float dd = (y < H_IMG - 1)  ? __ldg(depth + idx + W_IMG) : 0.0f;

    const float f = sf[0], invf = sf[1];

    float fx = (float)x, fy = (float)y;
    float d_u = 0.5f * (dr - dl);
    float d_v = 0.5f * (dd - du);
    float nx = f * d_u, ny = f * d_v;
    float nz = (960.0f - fx) * d_u + (720.0f - fy) * d_v - d;
    float nrm = sqrtf(nx * nx + ny * ny + nz * nz) + 1e-8f;
    float inv = 1.0f / (nrm * (d + 1e-8f));
    float ndx = nx * inv, ndy = ny * inv, ndz = nz * inv;
    float rx = (fx - 959.5f) * invf;
    float ry = (fy - 719.5f) * invf;
    float s = ndx * rx + ndy * ry + ndz;

    g_warp0[idx] = warp_one(t0, sM[0], sb[0], fx, fy, s);
    g_warp1[idx] = warp_one(t1, sM[1], sb[1], fx, fy, s);
}

// ---------------- two-pass dual-target ZNCC (4 CTAs/SM) — R11 layout ----------------
// smem layout (floats):
//   rawR  @ 0      (1952, stride 44, 44 rows)      [alive both passes]
//   rawT  @ 1952   (1952)                          [T0 pass1, T1 pass2]
//   rc    @ 3904   (1520, stride 40, 38 rows)      [alive both passes]
//   tc    @ 5424   (1520)
//   slotA @ 6944   (4192)
//   boxrr @ 11136  (1024)
#define SMEM_FLOATS 12160
#define OFF_RAWR  0
#define OFF_RAWT  1952
#define OFF_RC    3904
#define OFF_TC    5424
#define OFF_SLOT  6944
#define OFF_BOXRR 11136

__device__ __forceinline__ void z_h7(const float* __restrict__ raw, float* __restrict__ hs,
                                     int tid) {
    for (int i = tid; i < 440; i += ZBLK) {
        int row = i / 10, c0 = (i - row * 10) * 4;
        const float* src = raw + row * 44 + c0;
        float4 v0 = *(const float4*)(src);
        float4 v1 = *(const float4*)(src + 4);
        float4 v2 = *(const float4*)(src + 8);
        float s0 = v0.x + v0.y + v0.z + v0.w + v1.x + v1.y + v1.z;
        float s1 = s0 - v0.x + v1.w;
        float s2 = s1 - v0.y + v2.x;
        float s3 = s2 - v0.z + v2.y;
        *(float4*)(hs + row * 40 + c0) = make_float4(s0, s1, s2, s3);
    }
}

__device__ __forceinline__ void z_v7c(const float* __restrict__ hs,
                                      const float* __restrict__ raw,
                                      float* __restrict__ ct, int tid) {
    const float inv49 = 1.0f / 49.0f;
    for (int i = tid; i < 200; i += ZBLK) {
        int rg = i / 40, c = i - rg * 40;
        int r0 = rg * 8;
        int nout = 38 - r0;  if (nout > 8) nout = 8;
        const float* hsrc = hs + r0 * 40 + c;
        const float* rawF = raw + (r0 + 3) * 44 + (c + 3);
        float* dst = ct + r0 * 40 + c;
        float h[14];
        #pragma unroll
        for (int k = 0; k < 7; k++) h[k] = hsrc[k * 40];
        float s = h[0] + h[1] + h[2] + h[3] + h[4] + h[5] + h[6];
        dst[0] = rawF[0] - s * inv49;
        #pragma unroll
        for (int k = 1; k < 8; k++) {
            if (k < nout) {
                h[k + 6] = hsrc[(k + 6) * 40];
                s += h[k + 6] - h[k - 1];
                dst[k * 40] = rawF[k * 44] - s * inv49;
            }
        }
    }
}

__device__ __forceinline__ void z_prod_store(float* __restrict__ dst,
                                             const float* P, const float* Q, int row, int c0) {
    float p[10];
    #pragma unroll
    for (int j = 0; j < 10; j++) p[j] = P[j] * Q[j];
    float s0 = p[0]+p[1]+p[2]+p[3]+p[4]+p[5]+p[6];
    float s1 = s0 - p[0] + p[7], s2 = s1 - p[1] + p[8], s3 = s2 - p[2] + p[9];
    *(float4*)(dst + row * 32 + c0) = make_float4(s0, s1, s2, s3);
}

__device__ __forceinline__ void z_v7p(const float* __restrict__ pp, float* S) {
    float p0 = pp[0],   p1 = pp[32],  p2 = pp[64],  p3 = pp[96],  p4 = pp[128];
    float p5 = pp[160], p6 = pp[192], p7 = pp[224], p8 = pp[256], p9 = pp[288];
    S[0] = p0 + p1 + p2 + p3 + p4 + p5 + p6;
    S[1] = S[0] - p0 + p7;
    S[2] = S[1] - p1 + p8;
    S[3] = S[2] - p2 + p9;
}

__global__ __launch_bounds__(ZBLK, 4) void zncc2_kernel(const float* __restrict__ ref,
                                                        float* __restrict__ out) {
    extern __shared__ float sm[];
    __shared__ float redS[ZBLK / 32], redP[ZBLK / 32];

    const float inv49 = 1.0f / 49.0f;
    int tid = threadIdx.x;
    int gx0 = blockIdx.x * 32 - 6;
    int gy0 = blockIdx.y * 32 - 6;

    float score = 0.0f, pix = 0.0f;

    // ===== pass 1: ref + target 0 =====
    for (int i = tid; i < 44 * 44; i += ZBLK) {
        int r = i / 44, c = i - r * 44;
        int gx = gx0 + c, gy = gy0 + r;
        bool in = ((unsigned)gx < W_IMG) & ((unsigned)gy < H_IMG);
        size_t gi = in ? ((size_t)gy * W_IMG + gx) : 0;
        sm[OFF_RAWR + r * 44 + c] = in ? __ldg(ref + gi) : 0.0f;
        sm[OFF_RAWT + r * 44 + c] = in ? g_warp0[gi]     : 0.0f;
    }
    __syncthreads();

    for (int i = tid; i < 880; i += ZBLK) {
        int fi = i / 440, rem = i - fi * 440;
        int row = rem / 10, c0 = (rem - row * 10) * 4;
        const float* raw = sm + (fi ? OFF_RAWT : OFF_RAWR);
        float* hs = sm + OFF_SLOT + fi * 1760;
        const float* src = raw + row * 44 + c0;
        float4 v0 = *(const float4*)(src);
        float4 v1 = *(const float4*)(src + 4);
        float4 v2 = *(const float4*)(src + 8);
        float s0 = v0.x + v0.y + v0.z + v0.w + v1.x + v1.y + v1.z;
        float s1 = s0 - v0.x + v1.w;
        float s2 = s1 - v0.y + v2.x;
        float s3 = s2 - v0.z + v2.y;
        *(float4*)(hs + row * 40 + c0) = make_float4(s0, s1, s2, s3);
    }
    __syncthreads();

    for (int i = tid; i < 400; i += ZBLK) {
        int fi = i / 200, rem = i - fi * 200;
        int rg = rem / 40, c = rem - rg * 40;
        int r0 = rg * 8;
        int nout = 38 - r0;  if (nout > 8) nout = 8;
        const float* hsrc = sm + OFF_SLOT + fi * 1760 + r0 * 40 + c;
        const float* rawF = sm + (fi ? OFF_RAWT : OFF_RAWR) + (r0 + 3) * 44 + (c + 3);
        float* dst = sm + (fi ? OFF_TC : OFF_RC) + r0 * 40 + c;
        float h[14];
        #pragma unroll
        for (int k = 0; k < 7; k++) h[k] = hsrc[k * 40];
        float s = h[0] + h[1] + h[2] + h[3] + h[4] + h[5] + h[6];
        dst[0] = rawF[0] - s * inv49;
        #pragma unroll
        for (int k = 1; k < 8; k++) {
            if (k < nout) {
                h[k + 6] = hsrc[(k + 6) * 40];
                s += h[k + 6] - h[k - 1];
                dst[k * 40] = rawF[k * 44] - s * inv49;
            }
        }
    }
    __syncthreads();

    for (int i = tid; i < 304; i += ZBLK) {
        int row = i / 8, c0 = (i - row * 8) * 4;
        float A[12], B[12];
        #pragma unroll
        for (int j = 0; j < 12; j += 4) {
            float4 va = *(const float4*)(sm + OFF_RC + row * 40 + c0 + j);
            float4 vb = *(const float4*)(sm + OFF_TC + row * 40 + c0 + j);
            A[j] = va.x; A[j+1] = va.y; A[j+2] = va.z; A[j+3] = va.w;
            B[j] = vb.x; B[j+1] = vb.y; B[j+2] = vb.z; B[j+3] = vb.w;
        }
        z_prod_store(sm + OFF_SLOT,        A, A, row, c0);   // rr
        z_prod_store(sm + OFF_SLOT + 1216, A, B, row, c0);   // rt
        z_prod_store(sm + OFF_SLOT + 2432, B, B, row, c0);   // tt
    }
    __syncthreads();

    if (tid < 256) {
        int c = tid & 31, rg = tid >> 5;
        int r0 = rg * 4;
        float Srr[4], Srt[4], Stt[4];
        z_v7p(sm + OFF_SLOT        + r0 * 32 + c, Srr);
        z_v7p(sm + OFF_SLOT + 1216 + r0 * 32 + c, Srt);
        z_v7p(sm + OFF_SLOT + 2432 + r0 * 32 + c, Stt);
        #pragma unroll
        for (int k = 0; k < 4; k++) {
            int r = r0 + k;
            float boxr = Srr[k] * inv49;
            sm[OFF_BOXRR + r * 32 + c] = boxr;
            float t0c = sm[OFF_RAWT + (r + 6) * 44 + (c + 6)];
            float zm0 = (Srt[k] * inv49) / sqrtf(boxr * (Stt[k] * inv49) + 1e-8f);
            if (t0c != 0.0f) { score += zm0; pix += 1.0f; }
        }
    }
    __syncthreads();

    // ===== pass 2: target 1 =====
    for (int i = tid; i < 44 * 44; i += ZBLK) {
        int r = i / 44, c = i - r * 44;
        int gx = gx0 + c, gy = gy0 + r;
        bool in = ((unsigned)gx < W_IMG) & ((unsigned)gy < H_IMG);
        size_t gi = in ? ((size_t)gy * W_IMG + gx) : 0;
        sm[OFF_RAWT + r * 44 + c] = in ? g_warp1[gi] : 0.0f;
    }
    __syncthreads();

    z_h7(sm + OFF_RAWT, sm + OFF_SLOT, tid);
    __syncthreads();

    z_v7c(sm + OFF_SLOT, sm + OFF_RAWT, sm + OFF_TC, tid);
    __syncthreads();

    for (int i = tid; i < 304; i += ZBLK) {
        int row = i / 8, c0 = (i - row * 8) * 4;
        float A[12], B[12];
        #pragma unroll
        for (int j = 0; j < 12; j += 4) {
            float4 va = *(const float4*)(sm + OFF_RC + row * 40 + c0 + j);
            float4 vb = *(const float4*)(sm + OFF_TC + row * 40 + c0 + j);
            A[j] = va.x; A[j+1] = va.y; A[j+2] = va.z; A[j+3] = va.w;
            B[j] = vb.x; B[j+1] = vb.y; B[j+2] = vb.z; B[j+3] = vb.w;
        }
        z_prod_store(sm + OFF_SLOT + 1760, A, B, row, c0);   // rt
        z_prod_store(sm + OFF_SLOT + 2976, B, B, row, c0);   // tt
    }
    __syncthreads();

    if (tid < 256) {
        int c = tid & 31, rg = tid >> 5;
        int r0 = rg * 4;
        float Srt[4], Stt[4];
        z_v7p(sm + OFF_SLOT + 1760 + r0 * 32 + c, Srt);
        z_v7p(sm + OFF_SLOT + 2976 + r0 * 32 + c, Stt);
        #pragma unroll
        for (int k = 0; k < 4; k++) {
            int r = r0 + k;
            float boxr = sm[OFF_BOXRR + r * 32 + c];
            float t1c = sm[OFF_RAWT + (r + 6) * 44 + (c + 6)];
            float zm1 = (Srt[k] * inv49) / sqrtf(boxr * (Stt[k] * inv49) + 1e-8f);
            if (t1c != 0.0f) { score += zm1; pix += 1.0f; }
        }
    }

    // ===== reduction + finalize =====
    #pragma unroll
    for (int off = 16; off; off >>= 1) {
        score += __shfl_down_sync(0xFFFFFFFFu, score, off);
        pix   += __shfl_down_sync(0xFFFFFFFFu, pix,   off);
    }
    if ((tid & 31) == 0) { redS[tid >> 5] = score; redP[tid >> 5] = pix; }
    __syncthreads();
    if (tid == 0) {
        float s = 0.0f, p = 0.0f;
        #pragma unroll
        for (int i = 0; i < 8; i++) { s += redS[i]; p += redP[i]; }
        atomicAdd(&g_score, (double)s);
        atomicAdd(&g_pixels, (double)p);
        __threadfence();
        unsigned int nblk = gridDim.x * gridDim.y;
        unsigned int t = atomicAdd(&g_ticket, 1u);
        if (t == nblk - 1u) {
            double ts = atomicAdd(&g_score, 0.0);
            double tp = atomicAdd(&g_pixels, 0.0);
            double mean = ts / fmax(tp, 1.0);
            out[0] = (tp > 0.0) ? (float)(0.5 * (1.0 - mean)) : 0.0f;
            g_score  = 0.0;
            g_pixels = 0.0;
            __threadfence();
            g_ticket = 0u;
        }
    }
}

// ---------------- launch ----------------
extern "C" void kernel_launch(void* const* d_in, const int* in_sizes, int n_in,
                              void* d_out, int out_size) {
    const float* focal   = (const float*)d_in[0];
    const float* aa      = (const float*)d_in[1];
    const float* centers = (const float*)d_in[2];
    const float* ref     = (const float*)d_in[3];
    const float* depth   = (const float*)d_in[4];
    const float* tgts    = (const float*)d_in[5];

    static int smem_set = 0;
    if (!smem_set) {
        cudaFuncSetAttribute(zncc2_kernel, cudaFuncAttributeMaxDynamicSharedMemorySize,
                             SMEM_FLOATS * (int)sizeof(float));
        smem_set = 1;
    }

    warp2_kernel<<<(NPIX + 255) / 256, 256>>>(depth, tgts, tgts + (size_t)NPIX,
                                              focal, aa, centers);
    dim3 zg(W_IMG / 32, H_IMG / 32);
    zncc2_kernel<<<zg, ZBLK, SMEM_FLOATS * sizeof(float)>>>(ref, (float*)d_out);
}

// round 14
// speedup vs baseline: 1.0376x; 1.0376x over previous
#include <cuda_runtime.h>
#include <math.h>

#define H_IMG 1440
#define W_IMG 1920
#define NPIX (H_IMG * W_IMG)
#define ZBLK 512

// ---------------- device scratch ----------------
__device__ float  g_warp0[NPIX];
__device__ float  g_warp1[NPIX];
__device__ double g_score  = 0.0;
__device__ double g_pixels = 0.0;
__device__ unsigned int g_ticket = 0u;

// ---------------- fp32 setup math ----------------
__device__ __forceinline__ void rodrigues_f(const float* v, float R[3][3]) {
    float x = v[0], y = v[1], z = v[2];
    float th = sqrtf(x * x + y * y + z * z) + 1e-12f;
    float kx = x / th, ky = y / th, kz = z / th;
    float s = sinf(th), c = cosf(th), C = 1.0f - c;
    R[0][0] = c + C * kx * kx;       R[0][1] = C * kx * ky - s * kz;  R[0][2] = C * kx * kz + s * ky;
    R[1][0] = C * ky * kx + s * kz;  R[1][1] = c + C * ky * ky;       R[1][2] = C * ky * kz - s * kx;
    R[2][0] = C * kz * kx - s * ky;  R[2][1] = C * kz * ky + s * kx;  R[2][2] = c + C * kz * kz;
}

__device__ void compute_setup(const float* __restrict__ focal,
                              const float* __restrict__ aa,
                              const float* __restrict__ centers,
                              float sM[2][9], float sb[2][3], float* sf) {
    float f = focal[0];
    const float k02 = 960.0f - 0.5f;
    const float k12 = 720.0f - 0.5f;
    float invf = 1.0f / f;
    float Ki[3][3] = {{invf, 0.0f, -k02 * invf}, {0.0f, invf, -k12 * invf}, {0.0f, 0.0f, 1.0f}};
    float K [3][3] = {{f, 0.0f, k02}, {0.0f, f, k12}, {0.0f, 0.0f, 1.0f}};

    float R[3][3][3];
    #pragma unroll
    for (int i = 0; i < 3; i++) rodrigues_f(aa + 3 * i, R[i]);

    float M1[3][3];
    #pragma unroll
    for (int i = 0; i < 3; i++)
        #pragma unroll
        for (int j = 0; j < 3; j++) {
            float s = 0.0f;
            #pragma unroll
            for (int k = 0; k < 3; k++) s += R[0][k][i] * Ki[k][j];
            M1[i][j] = s;
        }

    #pragma unroll
    for (int t = 0; t < 2; t++) {
        float A[3][3];
        #pragma unroll
        for (int i = 0; i < 3; i++)
            #pragma unroll
            for (int j = 0; j < 3; j++) {
                float s = 0.0f;
                #pragma unroll
                for (int k = 0; k < 3; k++) s += K[i][k] * R[t + 1][k][j];
                A[i][j] = s;
            }
        #pragma unroll
        for (int i = 0; i < 3; i++)
            #pragma unroll
            for (int j = 0; j < 3; j++) {
                float s = 0.0f;
                #pragma unroll
                for (int k = 0; k < 3; k++) s += A[i][k] * M1[k][j];
                sM[t][3 * i + j] = s;
            }
        float Cd[3] = {centers[0] - centers[3 * (t + 1) + 0],
                       centers[1] - centers[3 * (t + 1) + 1],
                       centers[2] - centers[3 * (t + 1) + 2]};
        #pragma unroll
        for (int i = 0; i < 3; i++) {
            float s = 0.0f;
            #pragma unroll
            for (int k = 0; k < 3; k++) s += A[i][k] * Cd[k];
            sb[t][i] = s;
        }
    }
    sf[0] = f;
    sf[1] = invf;
}

// ---------------- warp (both targets, 2-wide) ----------------
__device__ __forceinline__ float tapf(const float* __restrict__ img, float xi, float yi) {
    bool valid = (xi >= 0.0f) & (xi <= (float)(W_IMG - 1)) &
                 (yi >= 0.0f) & (yi <= (float)(H_IMG - 1));
    if (!valid) return 0.0f;
    int xc = (int)xi;
    int yc = (int)yi;
    return __ldg(img + (size_t)yc * W_IMG + xc);
}

__device__ __forceinline__ float warp_one(const float* __restrict__ img,
                                          const float* M, const float* b,
                                          float fx, float fy, float s) {
    float w0 = M[0] * fx + M[1] * fy + M[2] + b[0] * s;
    float w1 = M[3] * fx + M[4] * fy + M[5] + b[1] * s;
    float w2 = M[6] * fx + M[7] * fy + M[8] + b[2] * s;
    float iz = 1.0f / (w2 + 1e-8f);
    float px = w0 * iz, py = w1 * iz;
    float x0 = floorf(px), y0 = floorf(py);
    float wx = px - x0, wy = py - y0;
    float v00 = tapf(img, x0,        y0);
    float v10 = tapf(img, x0 + 1.0f, y0);
    float v01 = tapf(img, x0,        y0 + 1.0f);
    float v11 = tapf(img, x0 + 1.0f, y0 + 1.0f);
    return (1.0f - wy) * (1.0f - wx) * v00 + (1.0f - wy) * wx * v10 +
           wy * (1.0f - wx) * v01 + wy * wx * v11;
}

__global__ __launch_bounds__(256) void warp2_kernel(const float* __restrict__ depth,
                                                    const float* __restrict__ t0,
                                                    const float* __restrict__ t1,
                                                    const float* __restrict__ focal,
                                                    const float* __restrict__ aa,
                                                    const float* __restrict__ centers) {
    __shared__ float sM[2][9];
    __shared__ float sb[2][3];
    __shared__ float sf[2];
    if (threadIdx.x == 0) compute_setup(focal, aa, centers, sM, sb, sf);
    __syncthreads();

    int g = blockIdx.x * blockDim.x + threadIdx.x;
    if (g < NPIX / 2) {
        int idx = g << 1;
        int x0 = idx % W_IMG, y = idx / W_IMG;

        float2 dc  = __ldg((const float2*)(depth + idx));
        float  dm  = (x0 > 0)             ? __ldg(depth + idx - 1) : 0.0f;
        float  dp  = (x0 + 2 < W_IMG)     ? __ldg(depth + idx + 2) : 0.0f;
        float2 dup = (y > 0)              ? __ldg((const float2*)(depth + idx - W_IMG))
                                          : make_float2(0.f, 0.f);
        float2 ddn = (y < H_IMG - 1)      ? __ldg((const float2*)(depth + idx + W_IMG))
                                          : make_float2(0.f, 0.f);
        float dce[4]  = {dm, dc.x, dc.y, dp};
        float dupA[2] = {dup.x, dup.y};
        float ddnA[2] = {ddn.x, ddn.y};

        const float f = sf[0], invf = sf[1];

        float o0[2], o1[2];
        float fy = (float)y;
        #pragma unroll
        for (int k = 0; k < 2; k++) {
            float fx = (float)(x0 + k);
            float d   = dce[k + 1];
            float d_u = 0.5f * (dce[k + 2] - dce[k]);
            float d_v = 0.5f * (ddnA[k] - dupA[k]);
            float nx = f * d_u, ny = f * d_v;
            float nz = (960.0f - fx) * d_u + (720.0f - fy) * d_v - d;
            float nrm = sqrtf(nx * nx + ny * ny + nz * nz) + 1e-8f;
            float inv = 1.0f / (nrm * (d + 1e-8f));
            float ndx = nx * inv, ndy = ny * inv, ndz = nz * inv;
            float rx = (fx - 959.5f) * invf;
            float ry = (fy - 719.5f) * invf;
            float s = ndx * rx + ndy * ry + ndz;
            o0[k] = warp_one(t0, sM[0], sb[0], fx, fy, s);
            o1[k] = warp_one(t1, sM[1], sb[1], fx, fy, s);
        }
        *(float2*)(g_warp0 + idx) = make_float2(o0[0], o0[1]);
        *(float2*)(g_warp1 + idx) = make_float2(o1[0], o1[1]);
    }
    // hint: allow dependent launch to proceed once this grid's stores flush
    cudaTriggerProgrammaticLaunchCompletion();
}

// ---------------- two-pass dual-target ZNCC (4 CTAs/SM) — R11 layout + PDL ----------------
// smem layout (floats):
//   rawR  @ 0      (1952, stride 44, 44 rows)      [alive both passes]
//   rawT  @ 1952   (1952)                          [T0 pass1, T1 pass2]
//   rc    @ 3904   (1520, stride 40, 38 rows)      [alive both passes]
//   tc    @ 5424   (1520)
//   slotA @ 6944   (4192)
//   boxrr @ 11136  (1024)
#define SMEM_FLOATS 12160
#define OFF_RAWR  0
#define OFF_RAWT  1952
#define OFF_RC    3904
#define OFF_TC    5424
#define OFF_SLOT  6944
#define OFF_BOXRR 11136

__device__ __forceinline__ void z_h7(const float* __restrict__ raw, float* __restrict__ hs,
                                     int tid) {
    for (int i = tid; i < 440; i += ZBLK) {
        int row = i / 10, c0 = (i - row * 10) * 4;
        const float* src = raw + row * 44 + c0;
        float4 v0 = *(const float4*)(src);
        float4 v1 = *(const float4*)(src + 4);
        float4 v2 = *(const float4*)(src + 8);
        float s0 = v0.x + v0.y + v0.z + v0.w + v1.x + v1.y + v1.z;
        float s1 = s0 - v0.x + v1.w;
        float s2 = s1 - v0.y + v2.x;
        float s3 = s2 - v0.z + v2.y;
        *(float4*)(hs + row * 40 + c0) = make_float4(s0, s1, s2, s3);
    }
}

__device__ __forceinline__ void z_v7c(const float* __restrict__ hs,
                                      const float* __restrict__ raw,
                                      float* __restrict__ ct, int tid) {
    const float inv49 = 1.0f / 49.0f;
    for (int i = tid; i < 200; i += ZBLK) {
        int rg = i / 40, c = i - rg * 40;
        int r0 = rg * 8;
        int nout = 38 - r0;  if (nout > 8) nout = 8;
        const float* hsrc = hs + r0 * 40 + c;
        const float* rawF = raw + (r0 + 3) * 44 + (c + 3);
        float* dst = ct + r0 * 40 + c;
        float h[14];
        #pragma unroll
        for (int k = 0; k < 7; k++) h[k] = hsrc[k * 40];
        float s = h[0] + h[1] + h[2] + h[3] + h[4] + h[5] + h[6];
        dst[0] = rawF[0] - s * inv49;
        #pragma unroll
        for (int k = 1; k < 8; k++) {
            if (k < nout) {
                h[k + 6] = hsrc[(k + 6) * 40];
                s += h[k + 6] - h[k - 1];
                dst[k * 40] = rawF[k * 44] - s * inv49;
            }
        }
    }
}

__device__ __forceinline__ void z_prod_store(float* __restrict__ dst,
                                             const float* P, const float* Q, int row, int c0) {
    float p[10];
    #pragma unroll
    for (int j = 0; j < 10; j++) p[j] = P[j] * Q[j];
    float s0 = p[0]+p[1]+p[2]+p[3]+p[4]+p[5]+p[6];
    float s1 = s0 - p[0] + p[7], s2 = s1 - p[1] + p[8], s3 = s2 - p[2] + p[9];
    *(float4*)(dst + row * 32 + c0) = make_float4(s0, s1, s2, s3);
}

__device__ __forceinline__ void z_v7p(const float* __restrict__ pp, float* S) {
    float p0 = pp[0],   p1 = pp[32],  p2 = pp[64],  p3 = pp[96],  p4 = pp[128];
    float p5 = pp[160], p6 = pp[192], p7 = pp[224], p8 = pp[256], p9 = pp[288];
    S[0] = p0 + p1 + p2 + p3 + p4 + p5 + p6;
    S[1] = S[0] - p0 + p7;
    S[2] = S[1] - p1 + p8;
    S[3] = S[2] - p2 + p9;
}

__global__ __launch_bounds__(ZBLK, 4) void zncc2_kernel(const float* __restrict__ ref,
                                                        float* __restrict__ out) {
    extern __shared__ float sm[];
    __shared__ float redS[ZBLK / 32], redP[ZBLK / 32];

    const float inv49 = 1.0f / 49.0f;
    int tid = threadIdx.x;
    int gx0 = blockIdx.x * 32 - 6;
    int gy0 = blockIdx.y * 32 - 6;

    float score = 0.0f, pix = 0.0f;

    // ===== ref-only pipeline (independent of warp kernel output) =====
    for (int i = tid; i < 44 * 44; i += ZBLK) {
        int r = i / 44, c = i - r * 44;
        int gx = gx0 + c, gy = gy0 + r;
        bool in = ((unsigned)gx < W_IMG) & ((unsigned)gy < H_IMG);
        sm[OFF_RAWR + r * 44 + c] = in ? __ldg(ref + (size_t)gy * W_IMG + gx) : 0.0f;
    }
    __syncthreads();

    z_h7(sm + OFF_RAWR, sm + OFF_SLOT, tid);           // hsR -> slot
    __syncthreads();

    z_v7c(sm + OFF_SLOT, sm + OFF_RAWR, sm + OFF_RC, tid);  // rc
    __syncthreads();

    // ===== wait for warp kernel's g_warp writes =====
    cudaGridDependencySynchronize();

    // ===== pass 1: target 0 =====
    for (int i = tid; i < 44 * 44; i += ZBLK) {
        int r = i / 44, c = i - r * 44;
        int gx = gx0 + c, gy = gy0 + r;
        bool in = ((unsigned)gx < W_IMG) & ((unsigned)gy < H_IMG);
        sm[OFF_RAWT + r * 44 + c] = in ? g_warp0[(size_t)gy * W_IMG + gx] : 0.0f;
    }
    __syncthreads();

    z_h7(sm + OFF_RAWT, sm + OFF_SLOT + 1760, tid);    // hsT
    __syncthreads();

    z_v7c(sm + OFF_SLOT + 1760, sm + OFF_RAWT, sm + OFF_TC, tid);
    __syncthreads();

    for (int i = tid; i < 304; i += ZBLK) {
        int row = i / 8, c0 = (i - row * 8) * 4;
        float A[12], B[12];
        #pragma unroll
        for (int j = 0; j < 12; j += 4) {
            float4 va = *(const float4*)(sm + OFF_RC + row * 40 + c0 + j);
            float4 vb = *(const float4*)(sm + OFF_TC + row * 40 + c0 + j);
            A[j] = va.x; A[j+1] = va.y; A[j+2] = va.z; A[j+3] = va.w;
            B[j] = vb.x; B[j+1] = vb.y; B[j+2] = vb.z; B[j+3] = vb.w;
        }
        z_prod_store(sm + OFF_SLOT,        A, A, row, c0);   // rr
        z_prod_store(sm + OFF_SLOT + 1216, A, B, row, c0);   // rt
        z_prod_store(sm + OFF_SLOT + 2432, B, B, row, c0);   // tt
    }
    __syncthreads();

    if (tid < 256) {
        int c = tid & 31, rg = tid >> 5;
        int r0 = rg * 4;
        float Srr[4], Srt[4], Stt[4];
        z_v7p(sm + OFF_SLOT        + r0 * 32 + c, Srr);
        z_v7p(sm + OFF_SLOT + 1216 + r0 * 32 + c, Srt);
        z_v7p(sm + OFF_SLOT + 2432 + r0 * 32 + c, Stt);
        #pragma unroll
        for (int k = 0; k < 4; k++) {
            int r = r0 + k;
            float boxr = Srr[k] * inv49;
            sm[OFF_BOXRR + r * 32 + c] = boxr;
            float t0c = sm[OFF_RAWT + (r + 6) * 44 + (c + 6)];
            float zm0 = (Srt[k] * inv49) / sqrtf(boxr * (Stt[k] * inv49) + 1e-8f);
            if (t0c != 0.0f) { score += zm0; pix += 1.0f; }
        }
    }
    __syncthreads();

    // ===== pass 2: target 1 =====
    for (int i = tid; i < 44 * 44; i += ZBLK) {
        int r = i / 44, c = i - r * 44;
        int gx = gx0 + c, gy = gy0 + r;
        bool in = ((unsigned)gx < W_IMG) & ((unsigned)gy < H_IMG);
        sm[OFF_RAWT + r * 44 + c] = in ? g_warp1[(size_t)gy * W_IMG + gx] : 0.0f;
    }
    __syncthreads();

    z_h7(sm + OFF_RAWT, sm + OFF_SLOT, tid);
    __syncthreads();

    z_v7c(sm + OFF_SLOT, sm + OFF_RAWT, sm + OFF_TC, tid);
    __syncthreads();

    for (int i = tid; i < 304; i += ZBLK) {
        int row = i / 8, c0 = (i - row * 8) * 4;
        float A[12], B[12];
        #pragma unroll
        for (int j = 0; j < 12; j += 4) {
            float4 va = *(const float4*)(sm + OFF_RC + row * 40 + c0 + j);
            float4 vb = *(const float4*)(sm + OFF_TC + row * 40 + c0 + j);
            A[j] = va.x; A[j+1] = va.y; A[j+2] = va.z; A[j+3] = va.w;
            B[j] = vb.x; B[j+1] = vb.y; B[j+2] = vb.z; B[j+3] = vb.w;
        }
        z_prod_store(sm + OFF_SLOT + 1760, A, B, row, c0);   // rt
        z_prod_store(sm + OFF_SLOT + 2976, B, B, row, c0);   // tt
    }
    __syncthreads();

    if (tid < 256) {
        int c = tid & 31, rg = tid >> 5;
        int r0 = rg * 4;
        float Srt[4], Stt[4];
        z_v7p(sm + OFF_SLOT + 1760 + r0 * 32 + c, Srt);
        z_v7p(sm + OFF_SLOT + 2976 + r0 * 32 + c, Stt);
        #pragma unroll
        for (int k = 0; k < 4; k++) {
            int r = r0 + k;
            float boxr = sm[OFF_BOXRR + r * 32 + c];
            float t1c = sm[OFF_RAWT + (r + 6) * 44 + (c + 6)];
            float zm1 = (Srt[k] * inv49) / sqrtf(boxr * (Stt[k] * inv49) + 1e-8f);
            if (t1c != 0.0f) { score += zm1; pix += 1.0f; }
        }
    }

    // ===== reduction + finalize =====
    #pragma unroll
    for (int off = 16; off; off >>= 1) {
        score += __shfl_down_sync(0xFFFFFFFFu, score, off);
        pix   += __shfl_down_sync(0xFFFFFFFFu, pix,   off);
    }
    if ((tid & 31) == 0) { redS[tid >> 5] = score; redP[tid >> 5] = pix; }
    __syncthreads();
    if (tid == 0) {
        float s = 0.0f, p = 0.0f;
        #pragma unroll
        for (int i = 0; i < 8; i++) { s += redS[i]; p += redP[i]; }
        atomicAdd(&g_score, (double)s);
        atomicAdd(&g_pixels, (double)p);
        __threadfence();
        unsigned int nblk = gridDim.x * gridDim.y;
        unsigned int t = atomicAdd(&g_ticket, 1u);
        if (t == nblk - 1u) {
            double ts = atomicAdd(&g_score, 0.0);
            double tp = atomicAdd(&g_pixels, 0.0);
            double mean = ts / fmax(tp, 1.0);
            out[0] = (tp > 0.0) ? (float)(0.5 * (1.0 - mean)) : 0.0f;
            g_score  = 0.0;
            g_pixels = 0.0;
            __threadfence();
            g_ticket = 0u;
        }
    }
}

// ---------------- launch: PDL overlap ----------------
extern "C" void kernel_launch(void* const* d_in, const int* in_sizes, int n_in,
                              void* d_out, int out_size) {
    const float* focal   = (const float*)d_in[0];
    const float* aa      = (const float*)d_in[1];
    const float* centers = (const float*)d_in[2];
    const float* ref     = (const float*)d_in[3];
    const float* depth   = (const float*)d_in[4];
    const float* tgts    = (const float*)d_in[5];

    static int smem_set = 0;
    if (!smem_set) {
        cudaFuncSetAttribute(zncc2_kernel, cudaFuncAttributeMaxDynamicSharedMemorySize,
                             SMEM_FLOATS * (int)sizeof(float));
        smem_set = 1;
    }

    warp2_kernel<<<(NPIX / 2 + 255) / 256, 256>>>(depth, tgts, tgts + (size_t)NPIX,
                                                  focal, aa, centers);

    cudaLaunchConfig_t cfg = {};
    cfg.gridDim = dim3(W_IMG / 32, H_IMG / 32);
    cfg.blockDim = dim3(ZBLK);
    cfg.dynamicSmemBytes = SMEM_FLOATS * sizeof(float);
    cfg.stream = 0;
    cudaLaunchAttribute attr[1];
    attr[0].id = cudaLaunchAttributeProgrammaticStreamSerialization;
    attr[0].val.programmaticStreamSerializationAllowed = 1;
    cfg.attrs = attr;
    cfg.numAttrs = 1;
    cudaLaunchKernelEx(&cfg, zncc2_kernel, ref, (float*)d_out);
}

// round 15
// speedup vs baseline: 1.1215x; 1.0808x over previous
#include <cuda_runtime.h>
#include <math.h>

#define H_IMG 1440
#define W_IMG 1920
#define NPIX (H_IMG * W_IMG)
#define ZBLK 512

// ---------------- device scratch ----------------
__device__ float  g_warp0[NPIX];
__device__ float  g_warp1[NPIX];
__device__ double g_score  = 0.0;
__device__ double g_pixels = 0.0;
__device__ unsigned int g_ticket = 0u;

// ---------------- fp32 setup math ----------------
__device__ __forceinline__ void rodrigues_f(const float* v, float R[3][3]) {
    float x = v[0], y = v[1], z = v[2];
    float th = sqrtf(x * x + y * y + z * z) + 1e-12f;
    float kx = x / th, ky = y / th, kz = z / th;
    float s = sinf(th), c = cosf(th), C = 1.0f - c;
    R[0][0] = c + C * kx * kx;       R[0][1] = C * kx * ky - s * kz;  R[0][2] = C * kx * kz + s * ky;
    R[1][0] = C * ky * kx + s * kz;  R[1][1] = c + C * ky * ky;       R[1][2] = C * ky * kz - s * kx;
    R[2][0] = C * kz * kx - s * ky;  R[2][1] = C * kz * ky + s * kx;  R[2][2] = c + C * kz * kz;
}

__device__ void compute_setup(const float* __restrict__ focal,
                              const float* __restrict__ aa,
                              const float* __restrict__ centers,
                              float sM[2][9], float sb[2][3], float* sf) {
    float f = focal[0];
    const float k02 = 960.0f - 0.5f;
    const float k12 = 720.0f - 0.5f;
    float invf = 1.0f / f;
    float Ki[3][3] = {{invf, 0.0f, -k02 * invf}, {0.0f, invf, -k12 * invf}, {0.0f, 0.0f, 1.0f}};
    float K [3][3] = {{f, 0.0f, k02}, {0.0f, f, k12}, {0.0f, 0.0f, 1.0f}};

    float R[3][3][3];
    #pragma unroll
    for (int i = 0; i < 3; i++) rodrigues_f(aa + 3 * i, R[i]);

    float M1[3][3];
    #pragma unroll
    for (int i = 0; i < 3; i++)
        #pragma unroll
        for (int j = 0; j < 3; j++) {
            float s = 0.0f;
            #pragma unroll
            for (int k = 0; k < 3; k++) s += R[0][k][i] * Ki[k][j];
            M1[i][j] = s;
        }

    #pragma unroll
    for (int t = 0; t < 2; t++) {
        float A[3][3];
        #pragma unroll
        for (int i = 0; i < 3; i++)
            #pragma unroll
            for (int j = 0; j < 3; j++) {
                float s = 0.0f;
                #pragma unroll
                for (int k = 0; k < 3; k++) s += K[i][k] * R[t + 1][k][j];
                A[i][j] = s;
            }
        #pragma unroll
        for (int i = 0; i < 3; i++)
            #pragma unroll
            for (int j = 0; j < 3; j++) {
                float s = 0.0f;
                #pragma unroll
                for (int k = 0; k < 3; k++) s += A[i][k] * M1[k][j];
                sM[t][3 * i + j] = s;
            }
        float Cd[3] = {centers[0] - centers[3 * (t + 1) + 0],
                       centers[1] - centers[3 * (t + 1) + 1],
                       centers[2] - centers[3 * (t + 1) + 2]};
        #pragma unroll
        for (int i = 0; i < 3; i++) {
            float s = 0.0f;
            #pragma unroll
            for (int k = 0; k < 3; k++) s += A[i][k] * Cd[k];
            sb[t][i] = s;
        }
    }
    sf[0] = f;
    sf[1] = invf;
}

// ---------------- warp (both targets, 2-wide) ----------------
__device__ __forceinline__ float tapf(const float* __restrict__ img, float xi, float yi) {
    bool valid = (xi >= 0.0f) & (xi <= (float)(W_IMG - 1)) &
                 (yi >= 0.0f) & (yi <= (float)(H_IMG - 1));
    if (!valid) return 0.0f;
    int xc = (int)xi;
    int yc = (int)yi;
    return __ldg(img + (size_t)yc * W_IMG + xc);
}

__device__ __forceinline__ float warp_one(const float* __restrict__ img,
                                          const float* M, const float* b,
                                          float fx, float fy, float s) {
    float w0 = M[0] * fx + M[1] * fy + M[2] + b[0] * s;
    float w1 = M[3] * fx + M[4] * fy + M[5] + b[1] * s;
    float w2 = M[6] * fx + M[7] * fy + M[8] + b[2] * s;
    float iz = 1.0f / (w2 + 1e-8f);
    float px = w0 * iz, py = w1 * iz;
    float x0 = floorf(px), y0 = floorf(py);
    float wx = px - x0, wy = py - y0;
    float v00 = tapf(img, x0,        y0);
    float v10 = tapf(img, x0 + 1.0f, y0);
    float v01 = tapf(img, x0,        y0 + 1.0f);
    float v11 = tapf(img, x0 + 1.0f, y0 + 1.0f);
    return (1.0f - wy) * (1.0f - wx) * v00 + (1.0f - wy) * wx * v10 +
           wy * (1.0f - wx) * v01 + wy * wx * v11;
}

__global__ __launch_bounds__(256, 6) void warp2_kernel(const float* __restrict__ depth,
                                                       const float* __restrict__ t0,
                                                       const float* __restrict__ t1,
                                                       const float* __restrict__ focal,
                                                       const float* __restrict__ aa,
                                                       const float* __restrict__ centers) {
    __shared__ float sM[2][9];
    __shared__ float sb[2][3];
    __shared__ float sf[2];
    if (threadIdx.x == 0) compute_setup(focal, aa, centers, sM, sb, sf);
    __syncthreads();

    int g = blockIdx.x * blockDim.x + threadIdx.x;
    if (g >= NPIX / 2) return;
    int idx = g << 1;
    int x0 = idx % W_IMG, y = idx / W_IMG;

    float2 dc  = __ldg((const float2*)(depth + idx));
    float  dm  = (x0 > 0)             ? __ldg(depth + idx - 1) : 0.0f;
    float  dp  = (x0 + 2 < W_IMG)     ? __ldg(depth + idx + 2) : 0.0f;
    float2 dup = (y > 0)              ? __ldg((const float2*)(depth + idx - W_IMG))
                                      : make_float2(0.f, 0.f);
    float2 ddn = (y < H_IMG - 1)      ? __ldg((const float2*)(depth + idx + W_IMG))
                                      : make_float2(0.f, 0.f);
    float dce[4]  = {dm, dc.x, dc.y, dp};
    float dupA[2] = {dup.x, dup.y};
    float ddnA[2] = {ddn.x, ddn.y};

    const float f = sf[0], invf = sf[1];

    float o0[2], o1[2];
    float fy = (float)y;
    #pragma unroll
    for (int k = 0; k < 2; k++) {
        float fx = (float)(x0 + k);
        float d   = dce[k + 1];
        float d_u = 0.5f * (dce[k + 2] - dce[k]);
        float d_v = 0.5f * (ddnA[k] - dupA[k]);
        float nx = f * d_u, ny = f * d_v;
        float nz = (960.0f - fx) * d_u + (720.0f - fy) * d_v - d;
        float nrm = sqrtf(nx * nx + ny * ny + nz * nz) + 1e-8f;
        float inv = 1.0f / (nrm * (d + 1e-8f));
        float ndx = nx * inv, ndy = ny * inv, ndz = nz * inv;
        float rx = (fx - 959.5f) * invf;
        float ry = (fy - 719.5f) * invf;
        float s = ndx * rx + ndy * ry + ndz;
        o0[k] = warp_one(t0, sM[0], sb[0], fx, fy, s);
        o1[k] = warp_one(t1, sM[1], sb[1], fx, fy, s);
    }
    *(float2*)(g_warp0 + idx) = make_float2(o0[0], o0[1]);
    *(float2*)(g_warp1 + idx) = make_float2(o1[0], o1[1]);
}

// ---------------- two-pass dual-target ZNCC (4 CTAs/SM) — R11 layout ----------------
// smem layout (floats):
//   rawR  @ 0      (1952, stride 44, 44 rows)      [alive both passes]
//   rawT  @ 1952   (1952)                          [T0 pass1, T1 pass2]
//   rc    @ 3904   (1520, stride 40, 38 rows)      [alive both passes]
//   tc    @ 5424   (1520)
//   slotA @ 6944   (4192)
//   boxrr @ 11136  (1024)
#define SMEM_FLOATS 12160
#define OFF_RAWR  0
#define OFF_RAWT  1952
#define OFF_RC    3904
#define OFF_TC    5424
#define OFF_SLOT  6944
#define OFF_BOXRR 11136

__device__ __forceinline__ void z_h7(const float* __restrict__ raw, float* __restrict__ hs,
                                     int tid) {
    for (int i = tid; i < 440; i += ZBLK) {
        int row = i / 10, c0 = (i - row * 10) * 4;
        const float* src = raw + row * 44 + c0;
        float4 v0 = *(const float4*)(src);
        float4 v1 = *(const float4*)(src + 4);
        float4 v2 = *(const float4*)(src + 8);
        float s0 = v0.x + v0.y + v0.z + v0.w + v1.x + v1.y + v1.z;
        float s1 = s0 - v0.x + v1.w;
        float s2 = s1 - v0.y + v2.x;
        float s3 = s2 - v0.z + v2.y;
        *(float4*)(hs + row * 40 + c0) = make_float4(s0, s1, s2, s3);
    }
}

__device__ __forceinline__ void z_v7c(const float* __restrict__ hs,
                                      const float* __restrict__ raw,
                                      float* __restrict__ ct, int tid) {
    const float inv49 = 1.0f / 49.0f;
    for (int i = tid; i < 200; i += ZBLK) {
        int rg = i / 40, c = i - rg * 40;
        int r0 = rg * 8;
        int nout = 38 - r0;  if (nout > 8) nout = 8;
        const float* hsrc = hs + r0 * 40 + c;
        const float* rawF = raw + (r0 + 3) * 44 + (c + 3);
        float* dst = ct + r0 * 40 + c;
        float h[14];
        #pragma unroll
        for (int k = 0; k < 7; k++) h[k] = hsrc[k * 40];
        float s = h[0] + h[1] + h[2] + h[3] + h[4] + h[5] + h[6];
        dst[0] = rawF[0] - s * inv49;
        #pragma unroll
        for (int k = 1; k < 8; k++) {
            if (k < nout) {
                h[k + 6] = hsrc[(k + 6) * 40];
                s += h[k + 6] - h[k - 1];
                dst[k * 40] = rawF[k * 44] - s * inv49;
            }
        }
    }
}

__device__ __forceinline__ void z_prod_store(float* __restrict__ dst,
                                             const float* P, const float* Q, int row, int c0) {
    float p[10];
    #pragma unroll
    for (int j = 0; j < 10; j++) p[j] = P[j] * Q[j];
    float s0 = p[0]+p[1]+p[2]+p[3]+p[4]+p[5]+p[6];
    float s1 = s0 - p[0] + p[7], s2 = s1 - p[1] + p[8], s3 = s2 - p[2] + p[9];
    *(float4*)(dst + row * 32 + c0) = make_float4(s0, s1, s2, s3);
}

__device__ __forceinline__ void z_v7p(const float* __restrict__ pp, float* S) {
    float p0 = pp[0],   p1 = pp[32],  p2 = pp[64],  p3 = pp[96],  p4 = pp[128];
    float p5 = pp[160], p6 = pp[192], p7 = pp[224], p8 = pp[256], p9 = pp[288];
    S[0] = p0 + p1 + p2 + p3 + p4 + p5 + p6;
    S[1] = S[0] - p0 + p7;
    S[2] = S[1] - p1 + p8;
    S[3] = S[2] - p2 + p9;
}

__global__ __launch_bounds__(ZBLK, 4) void zncc2_kernel(const float* __restrict__ ref,
                                                        float* __restrict__ out) {
    extern __shared__ float sm[];
    __shared__ float redS[ZBLK / 32], redP[ZBLK / 32];

    const float inv49 = 1.0f / 49.0f;
    int tid = threadIdx.x;
    int gx0 = blockIdx.x * 32 - 6;
    int gy0 = blockIdx.y * 32 - 6;

    float score = 0.0f, pix = 0.0f;

    // ===== pass 1: ref + target 0 =====
    for (int i = tid; i < 44 * 44; i += ZBLK) {
        int r = i / 44, c = i - r * 44;
        int gx = gx0 + c, gy = gy0 + r;
        bool in = ((unsigned)gx < W_IMG) & ((unsigned)gy < H_IMG);
        size_t gi = in ? ((size_t)gy * W_IMG + gx) : 0;
        sm[OFF_RAWR + r * 44 + c] = in ? __ldg(ref + gi) : 0.0f;
        sm[OFF_RAWT + r * 44 + c] = in ? g_warp0[gi]     : 0.0f;
    }
    __syncthreads();

    for (int i = tid; i < 880; i += ZBLK) {
        int fi = i / 440, rem = i - fi * 440;
        int row = rem / 10, c0 = (rem - row * 10) * 4;
        const float* raw = sm + (fi ? OFF_RAWT : OFF_RAWR);
        float* hs = sm + OFF_SLOT + fi * 1760;
        const float* src = raw + row * 44 + c0;
        float4 v0 = *(const float4*)(src);
        float4 v1 = *(const float4*)(src + 4);
        float4 v2 = *(const float4*)(src + 8);
        float s0 = v0.x + v0.y + v0.z + v0.w + v1.x + v1.y + v1.z;
        float s1 = s0 - v0.x + v1.w;
        float s2 = s1 - v0.y + v2.x;
        float s3 = s2 - v0.z + v2.y;
        *(float4*)(hs + row * 40 + c0) = make_float4(s0, s1, s2, s3);
    }
    __syncthreads();

    for (int i = tid; i < 400; i += ZBLK) {
        int fi = i / 200, rem = i - fi * 200;
        int rg = rem / 40, c = rem - rg * 40;
        int r0 = rg * 8;
        int nout = 38 - r0;  if (nout > 8) nout = 8;
        const float* hsrc = sm + OFF_SLOT + fi * 1760 + r0 * 40 + c;
        const float* rawF = sm + (fi ? OFF_RAWT : OFF_RAWR) + (r0 + 3) * 44 + (c + 3);
        float* dst = sm + (fi ? OFF_TC : OFF_RC) + r0 * 40 + c;
        float h[14];
        #pragma unroll
        for (int k = 0; k < 7; k++) h[k] = hsrc[k * 40];
        float s = h[0] + h[1] + h[2] + h[3] + h[4] + h[5] + h[6];
        dst[0] = rawF[0] - s * inv49;
        #pragma unroll
        for (int k = 1; k < 8; k++) {
            if (k < nout) {
                h[k + 6] = hsrc[(k + 6) * 40];
                s += h[k + 6] - h[k - 1];
                dst[k * 40] = rawF[k * 44] - s * inv49;
            }
        }
    }
    __syncthreads();

    for (int i = tid; i < 304; i += ZBLK) {
        int row = i / 8, c0 = (i - row * 8) * 4;
        float A[12], B[12];
        #pragma unroll
        for (int j = 0; j < 12; j += 4) {
            float4 va = *(const float4*)(sm + OFF_RC + row * 40 + c0 + j);
            float4 vb = *(const float4*)(sm + OFF_TC + row * 40 + c0 + j);
            A[j] = va.x; A[j+1] = va.y; A[j+2] = va.z; A[j+3] = va.w;
            B[j] = vb.x; B[j+1] = vb.y; B[j+2] = vb.z; B[j+3] = vb.w;
        }
        z_prod_store(sm + OFF_SLOT,        A, A, row, c0);   // rr
        z_prod_store(sm + OFF_SLOT + 1216, A, B, row, c0);   // rt
        z_prod_store(sm + OFF_SLOT + 2432, B, B, row, c0);   // tt
    }
    __syncthreads();

    if (tid < 256) {
        int c = tid & 31, rg = tid >> 5;
        int r0 = rg * 4;
        float Srr[4], Srt[4], Stt[4];
        z_v7p(sm + OFF_SLOT        + r0 * 32 + c, Srr);
        z_v7p(sm + OFF_SLOT + 1216 + r0 * 32 + c, Srt);
        z_v7p(sm + OFF_SLOT + 2432 + r0 * 32 + c, Stt);
        #pragma unroll
        for (int k = 0; k < 4; k++) {
            int r = r0 + k;
            float boxr = Srr[k] * inv49;
            sm[OFF_BOXRR + r * 32 + c] = boxr;
            float t0c = sm[OFF_RAWT + (r + 6) * 44 + (c + 6)];
            float zm0 = (Srt[k] * inv49) / sqrtf(boxr * (Stt[k] * inv49) + 1e-8f);
            if (t0c != 0.0f) { score += zm0; pix += 1.0f; }
        }
    }
    __syncthreads();

    // ===== pass 2: target 1 =====
    for (int i = tid; i < 44 * 44; i += ZBLK) {
        int r = i / 44, c = i - r * 44;
        int gx = gx0 + c, gy = gy0 + r;
        bool in = ((unsigned)gx < W_IMG) & ((unsigned)gy < H_IMG);
        size_t gi = in ? ((size_t)gy * W_IMG + gx) : 0;
        sm[OFF_RAWT + r * 44 + c] = in ? g_warp1[gi] : 0.0f;
    }
    __syncthreads();

    z_h7(sm + OFF_RAWT, sm + OFF_SLOT, tid);
    __syncthreads();

    z_v7c(sm + OFF_SLOT, sm + OFF_RAWT, sm + OFF_TC, tid);
    __syncthreads();

    for (int i = tid; i < 304; i += ZBLK) {
        int row = i / 8, c0 = (i - row * 8) * 4;
        float A[12], B[12];
        #pragma unroll
        for (int j = 0; j < 12; j += 4) {
            float4 va = *(const float4*)(sm + OFF_RC + row * 40 + c0 + j);
            float4 vb = *(const float4*)(sm + OFF_TC + row * 40 + c0 + j);
            A[j] = va.x; A[j+1] = va.y; A[j+2] = va.z; A[j+3] = va.w;
            B[j] = vb.x; B[j+1] = vb.y; B[j+2] = vb.z; B[j+3] = vb.w;
        }
        z_prod_store(sm + OFF_SLOT + 1760, A, B, row, c0);   // rt
        z_prod_store(sm + OFF_SLOT + 2976, B, B, row, c0);   // tt
    }
    __syncthreads();

    if (tid < 256) {
        int c = tid & 31, rg = tid >> 5;
        int r0 = rg * 4;
        float Srt[4], Stt[4];
        z_v7p(sm + OFF_SLOT + 1760 + r0 * 32 + c, Srt);
        z_v7p(sm + OFF_SLOT + 2976 + r0 * 32 + c, Stt);
        #pragma unroll
        for (int k = 0; k < 4; k++) {
            int r = r0 + k;
            float boxr = sm[OFF_BOXRR + r * 32 + c];
            float t1c = sm[OFF_RAWT + (r + 6) * 44 + (c + 6)];
            float zm1 = (Srt[k] * inv49) / sqrtf(boxr * (Stt[k] * inv49) + 1e-8f);
            if (t1c != 0.0f) { score += zm1; pix += 1.0f; }
        }
    }

    // ===== reduction + finalize =====
    #pragma unroll
    for (int off = 16; off; off >>= 1) {
        score += __shfl_down_sync(0xFFFFFFFFu, score, off);
        pix   += __shfl_down_sync(0xFFFFFFFFu, pix,   off);
    }
    if ((tid & 31) == 0) { redS[tid >> 5] = score; redP[tid >> 5] = pix; }
    __syncthreads();
    if (tid == 0) {
        float s = 0.0f, p = 0.0f;
        #pragma unroll
        for (int i = 0; i < 8; i++) { s += redS[i]; p += redP[i]; }
        atomicAdd(&g_score, (double)s);
        atomicAdd(&g_pixels, (double)p);
        __threadfence();
        unsigned int nblk = gridDim.x * gridDim.y;
        unsigned int t = atomicAdd(&g_ticket, 1u);
        if (t == nblk - 1u) {
            double ts = atomicAdd(&g_score, 0.0);
            double tp = atomicAdd(&g_pixels, 0.0);
            double mean = ts / fmax(tp, 1.0);
            out[0] = (tp > 0.0) ? (float)(0.5 * (1.0 - mean)) : 0.0f;
            g_score  = 0.0;
            g_pixels = 0.0;
            __threadfence();
            g_ticket = 0u;
        }
    }
}

// ---------------- launch ----------------
extern "C" void kernel_launch(void* const* d_in, const int* in_sizes, int n_in,
                              void* d_out, int out_size) {
    const float* focal   = (const float*)d_in[0];
    const float* aa      = (const float*)d_in[1];
    const float* centers = (const float*)d_in[2];
    const float* ref     = (const float*)d_in[3];
    const float* depth   = (const float*)d_in[4];
    const float* tgts    = (const float*)d_in[5];

    static int smem_set = 0;
    if (!smem_set) {
        cudaFuncSetAttribute(zncc2_kernel, cudaFuncAttributeMaxDynamicSharedMemorySize,
                             SMEM_FLOATS * (int)sizeof(float));
        smem_set = 1;
    }

    warp2_kernel<<<(NPIX / 2 + 255) / 256, 256>>>(depth, tgts, tgts + (size_t)NPIX,
                                                  focal, aa, centers);
    dim3 zg(W_IMG / 32, H_IMG / 32);
    zncc2_kernel<<<zg, ZBLK, SMEM_FLOATS * sizeof(float)>>>(ref, (float*)d_out);
}

// round 16
// speedup vs baseline: 1.1470x; 1.0228x over previous
#include <cuda_runtime.h>
#include <math.h>

#define H_IMG 1440
#define W_IMG 1920
#define NPIX (H_IMG * W_IMG)
#define ZBLK 512

// ---------------- device scratch ----------------
__device__ float  g_warp0[NPIX];
__device__ float  g_warp1[NPIX];
__device__ double g_score  = 0.0;
__device__ double g_pixels = 0.0;
__device__ unsigned int g_ticket = 0u;

// ---------------- fp32 setup math ----------------
__device__ __forceinline__ void rodrigues_f(const float* v, float R[3][3]) {
    float x = v[0], y = v[1], z = v[2];
    float th = sqrtf(x * x + y * y + z * z) + 1e-12f;
    float kx = x / th, ky = y / th, kz = z / th;
    float s = sinf(th), c = cosf(th), C = 1.0f - c;
    R[0][0] = c + C * kx * kx;       R[0][1] = C * kx * ky - s * kz;  R[0][2] = C * kx * kz + s * ky;
    R[1][0] = C * ky * kx + s * kz;  R[1][1] = c + C * ky * ky;       R[1][2] = C * ky * kz - s * kx;
    R[2][0] = C * kz * kx - s * ky;  R[2][1] = C * kz * ky + s * kx;  R[2][2] = c + C * kz * kz;
}

__device__ void compute_setup(const float* __restrict__ focal,
                              const float* __restrict__ aa,
                              const float* __restrict__ centers,
                              float sM[2][9], float sb[2][3], float* sf) {
    float f = focal[0];
    const float k02 = 960.0f - 0.5f;
    const float k12 = 720.0f - 0.5f;
    float invf = 1.0f / f;
    float Ki[3][3] = {{invf, 0.0f, -k02 * invf}, {0.0f, invf, -k12 * invf}, {0.0f, 0.0f, 1.0f}};
    float K [3][3] = {{f, 0.0f, k02}, {0.0f, f, k12}, {0.0f, 0.0f, 1.0f}};

    float R[3][3][3];
    #pragma unroll
    for (int i = 0; i < 3; i++) rodrigues_f(aa + 3 * i, R[i]);

    float M1[3][3];
    #pragma unroll
    for (int i = 0; i < 3; i++)
        #pragma unroll
        for (int j = 0; j < 3; j++) {
            float s = 0.0f;
            #pragma unroll
            for (int k = 0; k < 3; k++) s += R[0][k][i] * Ki[k][j];
            M1[i][j] = s;
        }

    #pragma unroll
    for (int t = 0; t < 2; t++) {
        float A[3][3];
        #pragma unroll
        for (int i = 0; i < 3; i++)
            #pragma unroll
            for (int j = 0; j < 3; j++) {
                float s = 0.0f;
                #pragma unroll
                for (int k = 0; k < 3; k++) s += K[i][k] * R[t + 1][k][j];
                A[i][j] = s;
            }
        #pragma unroll
        for (int i = 0; i < 3; i++)
            #pragma unroll
            for (int j = 0; j < 3; j++) {
                float s = 0.0f;
                #pragma unroll
                for (int k = 0; k < 3; k++) s += A[i][k] * M1[k][j];
                sM[t][3 * i + j] = s;
            }
        float Cd[3] = {centers[0] - centers[3 * (t + 1) + 0],
                       centers[1] - centers[3 * (t + 1) + 1],
                       centers[2] - centers[3 * (t + 1) + 2]};
        #pragma unroll
        for (int i = 0; i < 3; i++) {
            float s = 0.0f;
            #pragma unroll
            for (int k = 0; k < 3; k++) s += A[i][k] * Cd[k];
            sb[t][i] = s;
        }
    }
    sf[0] = f;
    sf[1] = invf;
}

// ---------------- warp (both targets, 2-wide) ----------------
__device__ __forceinline__ float tapf(const float* __restrict__ img, float xi, float yi) {
    bool valid = (xi >= 0.0f) & (xi <= (float)(W_IMG - 1)) &
                 (yi >= 0.0f) & (yi <= (float)(H_IMG - 1));
    if (!valid) return 0.0f;
    int xc = (int)xi;
    int yc = (int)yi;
    return __ldg(img + (size_t)yc * W_IMG + xc);
}

__device__ __forceinline__ float warp_one(const float* __restrict__ img,
                                          const float* M, const float* b,
                                          float fx, float fy, float s) {
    float w0 = M[0] * fx + M[1] * fy + M[2] + b[0] * s;
    float w1 = M[3] * fx + M[4] * fy + M[5] + b[1] * s;
    float w2 = M[6] * fx + M[7] * fy + M[8] + b[2] * s;
    float iz = 1.0f / (w2 + 1e-8f);
    float px = w0 * iz, py = w1 * iz;
    float x0 = floorf(px), y0 = floorf(py);
    float wx = px - x0, wy = py - y0;
    float v00 = tapf(img, x0,        y0);
    float v10 = tapf(img, x0 + 1.0f, y0);
    float v01 = tapf(img, x0,        y0 + 1.0f);
    float v11 = tapf(img, x0 + 1.0f, y0 + 1.0f);
    return (1.0f - wy) * (1.0f - wx) * v00 + (1.0f - wy) * wx * v10 +
           wy * (1.0f - wx) * v01 + wy * wx * v11;
}

__global__ __launch_bounds__(256, 6) void warp2_kernel(const float* __restrict__ depth,
                                                       const float* __restrict__ t0,
                                                       const float* __restrict__ t1,
                                                       const float* __restrict__ focal,
                                                       const float* __restrict__ aa,
                                                       const float* __restrict__ centers) {
    __shared__ float sM[2][9];
    __shared__ float sb[2][3];
    __shared__ float sf[2];
    if (threadIdx.x == 0) compute_setup(focal, aa, centers, sM, sb, sf);
    __syncthreads();

    int g = blockIdx.x * blockDim.x + threadIdx.x;
    if (g >= NPIX / 2) return;
    int idx = g << 1;
    int x0 = idx % W_IMG, y = idx / W_IMG;

    float2 dc  = __ldg((const float2*)(depth + idx));
    float  dm  = (x0 > 0)             ? __ldg(depth + idx - 1) : 0.0f;
    float  dp  = (x0 + 2 < W_IMG)     ? __ldg(depth + idx + 2) : 0.0f;
    float2 dup = (y > 0)              ? __ldg((const float2*)(depth + idx - W_IMG))
                                      : make_float2(0.f, 0.f);
    float2 ddn = (y < H_IMG - 1)      ? __ldg((const float2*)(depth + idx + W_IMG))
                                      : make_float2(0.f, 0.f);
    float dce[4]  = {dm, dc.x, dc.y, dp};
    float dupA[2] = {dup.x, dup.y};
    float ddnA[2] = {ddn.x, ddn.y};

    const float f = sf[0], invf = sf[1];

    float o0[2], o1[2];
    float fy = (float)y;
    #pragma unroll
    for (int k = 0; k < 2; k++) {
        float fx = (float)(x0 + k);
        float d   = dce[k + 1];
        float d_u = 0.5f * (dce[k + 2] - dce[k]);
        float d_v = 0.5f * (ddnA[k] - dupA[k]);
        float nx = f * d_u, ny = f * d_v;
        float nz = (960.0f - fx) * d_u + (720.0f - fy) * d_v - d;
        float nrm = sqrtf(nx * nx + ny * ny + nz * nz) + 1e-8f;
        float inv = 1.0f / (nrm * (d + 1e-8f));
        float ndx = nx * inv, ndy = ny * inv, ndz = nz * inv;
        float rx = (fx - 959.5f) * invf;
        float ry = (fy - 719.5f) * invf;
        float s = ndx * rx + ndy * ry + ndz;
        o0[k] = warp_one(t0, sM[0], sb[0], fx, fy, s);
        o1[k] = warp_one(t1, sM[1], sb[1], fx, fy, s);
    }
    *(float2*)(g_warp0 + idx) = make_float2(o0[0], o0[1]);
    *(float2*)(g_warp1 + idx) = make_float2(o1[0], o1[1]);
}

// ---------------- two-pass dual-target ZNCC (4 CTAs/SM) — R11 layout ----------------
// smem layout (floats):
//   rawR  @ 0      (1952, stride 44, 44 rows)      [alive both passes]
//   rawT  @ 1952   (1952)                          [T0 pass1, T1 pass2]
//   rc    @ 3904   (1520, stride 40, 38 rows)      [alive both passes]
//   tc    @ 5424   (1520)
//   slotA @ 6944   (4192)
//   boxrr @ 11136  (1024)
#define SMEM_FLOATS 12160
#define OFF_RAWR  0
#define OFF_RAWT  1952
#define OFF_RC    3904
#define OFF_TC    5424
#define OFF_SLOT  6944
#define OFF_BOXRR 11136

__device__ __forceinline__ void z_h7(const float* __restrict__ raw, float* __restrict__ hs,
                                     int tid) {
    for (int i = tid; i < 440; i += ZBLK) {
        int row = i / 10, c0 = (i - row * 10) * 4;
        const float* src = raw + row * 44 + c0;
        float4 v0 = *(const float4*)(src);
        float4 v1 = *(const float4*)(src + 4);
        float4 v2 = *(const float4*)(src + 8);
        float s0 = v0.x + v0.y + v0.z + v0.w + v1.x + v1.y + v1.z;
        float s1 = s0 - v0.x + v1.w;
        float s2 = s1 - v0.y + v2.x;
        float s3 = s2 - v0.z + v2.y;
        *(float4*)(hs + row * 40 + c0) = make_float4(s0, s1, s2, s3);
    }
}

__device__ __forceinline__ void z_v7c(const float* __restrict__ hs,
                                      const float* __restrict__ raw,
                                      float* __restrict__ ct, int tid) {
    const float inv49 = 1.0f / 49.0f;
    for (int i = tid; i < 200; i += ZBLK) {
        int rg = i / 40, c = i - rg * 40;
        int r0 = rg * 8;
        int nout = 38 - r0;  if (nout > 8) nout = 8;
        const float* hsrc = hs + r0 * 40 + c;
        const float* rawF = raw + (r0 + 3) * 44 + (c + 3);
        float* dst = ct + r0 * 40 + c;
        float h[14];
        #pragma unroll
        for (int k = 0; k < 7; k++) h[k] = hsrc[k * 40];
        float s = h[0] + h[1] + h[2] + h[3] + h[4] + h[5] + h[6];
        dst[0] = rawF[0] - s * inv49;
        #pragma unroll
        for (int k = 1; k < 8; k++) {
            if (k < nout) {
                h[k + 6] = hsrc[(k + 6) * 40];
                s += h[k + 6] - h[k - 1];
                dst[k * 40] = rawF[k * 44] - s * inv49;
            }
        }
    }
}

__device__ __forceinline__ void z_prod_store(float* __restrict__ dst,
                                             const float* P, const float* Q, int row, int c0) {
    float p[10];
    #pragma unroll
    for (int j = 0; j < 10; j++) p[j] = P[j] * Q[j];
    float s0 = p[0]+p[1]+p[2]+p[3]+p[4]+p[5]+p[6];
    float s1 = s0 - p[0] + p[7], s2 = s1 - p[1] + p[8], s3 = s2 - p[2] + p[9];
    *(float4*)(dst + row * 32 + c0) = make_float4(s0, s1, s2, s3);
}

__device__ __forceinline__ void z_v7p(const float* __restrict__ pp, float* S) {
    float p0 = pp[0],   p1 = pp[32],  p2 = pp[64],  p3 = pp[96],  p4 = pp[128];
    float p5 = pp[160], p6 = pp[192], p7 = pp[224], p8 = pp[256], p9 = pp[288];
    S[0] = p0 + p1 + p2 + p3 + p4 + p5 + p6;
    S[1] = S[0] - p0 + p7;
    S[2] = S[1] - p1 + p8;
    S[3] = S[2] - p2 + p9;
}

__global__ __launch_bounds__(ZBLK, 4) void zncc2_kernel(const float* __restrict__ ref,
                                                        float* __restrict__ out) {
    extern __shared__ float sm[];
    __shared__ float redS[ZBLK / 32], redP[ZBLK / 32];

    const float inv49 = 1.0f / 49.0f;
    int tid = threadIdx.x;
    int gx0 = blockIdx.x * 32 - 6;
    int gy0 = blockIdx.y * 32 - 6;
    bool xfast = (gx0 >= 0) & (gx0 + 43 < W_IMG);

    float score = 0.0f, pix = 0.0f;

    // ===== pass 1: ref + target 0 (float2-vectorized halo load) =====
    for (int i = tid; i < 44 * 22; i += ZBLK) {
        int r = i / 22, q = i - r * 22;
        int gy = gy0 + r;
        int gx = gx0 + 2 * q;
        float2 vR = make_float2(0.f, 0.f);
        float2 v0 = make_float2(0.f, 0.f);
        if ((unsigned)gy < (unsigned)H_IMG) {
            size_t gi = (size_t)gy * W_IMG + gx;
            if (xfast) {
                vR = __ldg((const float2*)(ref + gi));
                v0 = *(const float2*)(g_warp0 + gi);
            } else {
                if ((unsigned)gx < (unsigned)W_IMG) {
                    vR.x = __ldg(ref + gi); v0.x = g_warp0[gi];
                }
                if ((unsigned)(gx + 1) < (unsigned)W_IMG) {
                    vR.y = __ldg(ref + gi + 1); v0.y = g_warp0[gi + 1];
                }
            }
        }
        int so = r * 44 + 2 * q;
        *(float2*)(sm + OFF_RAWR + so) = vR;
        *(float2*)(sm + OFF_RAWT + so) = v0;
    }
    __syncthreads();

    for (int i = tid; i < 880; i += ZBLK) {
        int fi = i / 440, rem = i - fi * 440;
        int row = rem / 10, c0 = (rem - row * 10) * 4;
        const float* raw = sm + (fi ? OFF_RAWT : OFF_RAWR);
        float* hs = sm + OFF_SLOT + fi * 1760;
        const float* src = raw + row * 44 + c0;
        float4 v0 = *(const float4*)(src);
        float4 v1 = *(const float4*)(src + 4);
        float4 v2 = *(const float4*)(src + 8);
        float s0 = v0.x + v0.y + v0.z + v0.w + v1.x + v1.y + v1.z;
        float s1 = s0 - v0.x + v1.w;
        float s2 = s1 - v0.y + v2.x;
        float s3 = s2 - v0.z + v2.y;
        *(float4*)(hs + row * 40 + c0) = make_float4(s0, s1, s2, s3);
    }
    __syncthreads();

    for (int i = tid; i < 400; i += ZBLK) {
        int fi = i / 200, rem = i - fi * 200;
        int rg = rem / 40, c = rem - rg * 40;
        int r0 = rg * 8;
        int nout = 38 - r0;  if (nout > 8) nout = 8;
        const float* hsrc = sm + OFF_SLOT + fi * 1760 + r0 * 40 + c;
        const float* rawF = sm + (fi ? OFF_RAWT : OFF_RAWR) + (r0 + 3) * 44 + (c + 3);
        float* dst = sm + (fi ? OFF_TC : OFF_RC) + r0 * 40 + c;
        float h[14];
        #pragma unroll
        for (int k = 0; k < 7; k++) h[k] = hsrc[k * 40];
        float s = h[0] + h[1] + h[2] + h[3] + h[4] + h[5] + h[6];
        dst[0] = rawF[0] - s * inv49;
        #pragma unroll
        for (int k = 1; k < 8; k++) {
            if (k < nout) {
                h[k + 6] = hsrc[(k + 6) * 40];
                s += h[k + 6] - h[k - 1];
                dst[k * 40] = rawF[k * 44] - s * inv49;
            }
        }
    }
    __syncthreads();

    for (int i = tid; i < 304; i += ZBLK) {
        int row = i / 8, c0 = (i - row * 8) * 4;
        float A[12], B[12];
        #pragma unroll
        for (int j = 0; j < 12; j += 4) {
            float4 va = *(const float4*)(sm + OFF_RC + row * 40 + c0 + j);
            float4 vb = *(const float4*)(sm + OFF_TC + row * 40 + c0 + j);
            A[j] = va.x; A[j+1] = va.y; A[j+2] = va.z; A[j+3] = va.w;
            B[j] = vb.x; B[j+1] = vb.y; B[j+2] = vb.z; B[j+3] = vb.w;
        }
        z_prod_store(sm + OFF_SLOT,        A, A, row, c0);   // rr
        z_prod_store(sm + OFF_SLOT + 1216, A, B, row, c0);   // rt
        z_prod_store(sm + OFF_SLOT + 2432, B, B, row, c0);   // tt
    }
    __syncthreads();

    if (tid < 256) {
        int c = tid & 31, rg = tid >> 5;
        int r0 = rg * 4;
        float Srr[4], Srt[4], Stt[4];
        z_v7p(sm + OFF_SLOT        + r0 * 32 + c, Srr);
        z_v7p(sm + OFF_SLOT + 1216 + r0 * 32 + c, Srt);
        z_v7p(sm + OFF_SLOT + 2432 + r0 * 32 + c, Stt);
        #pragma unroll
        for (int k = 0; k < 4; k++) {
            int r = r0 + k;
            float boxr = Srr[k] * inv49;
            sm[OFF_BOXRR + r * 32 + c] = boxr;
            float t0c = sm[OFF_RAWT + (r + 6) * 44 + (c + 6)];
            float zm0 = (Srt[k] * inv49) / sqrtf(boxr * (Stt[k] * inv49) + 1e-8f);
            if (t0c != 0.0f) { score += zm0; pix += 1.0f; }
        }
    }
    __syncthreads();

    // ===== pass 2: target 1 (float2-vectorized halo load) =====
    for (int i = tid; i < 44 * 22; i += ZBLK) {
        int r = i / 22, q = i - r * 22;
        int gy = gy0 + r;
        int gx = gx0 + 2 * q;
        float2 v1 = make_float2(0.f, 0.f);
        if ((unsigned)gy < (unsigned)H_IMG) {
            size_t gi = (size_t)gy * W_IMG + gx;
            if (xfast) {
                v1 = *(const float2*)(g_warp1 + gi);
            } else {
                if ((unsigned)gx < (unsigned)W_IMG)       v1.x = g_warp1[gi];
                if ((unsigned)(gx + 1) < (unsigned)W_IMG) v1.y = g_warp1[gi + 1];
            }
        }
        *(float2*)(sm + OFF_RAWT + r * 44 + 2 * q) = v1;
    }
    __syncthreads();

    z_h7(sm + OFF_RAWT, sm + OFF_SLOT, tid);
    __syncthreads();

    z_v7c(sm + OFF_SLOT, sm + OFF_RAWT, sm + OFF_TC, tid);
    __syncthreads();

    for (int i = tid; i < 304; i += ZBLK) {
        int row = i / 8, c0 = (i - row * 8) * 4;
        float A[12], B[12];
        #pragma unroll
        for (int j = 0; j < 12; j += 4) {
            float4 va = *(const float4*)(sm + OFF_RC + row * 40 + c0 + j);
            float4 vb = *(const float4*)(sm + OFF_TC + row * 40 + c0 + j);
            A[j] = va.x; A[j+1] = va.y; A[j+2] = va.z; A[j+3] = va.w;
            B[j] = vb.x; B[j+1] = vb.y; B[j+2] = vb.z; B[j+3] = vb.w;
        }
        z_prod_store(sm + OFF_SLOT + 1760, A, B, row, c0);   // rt
        z_prod_store(sm + OFF_SLOT + 2976, B, B, row, c0);   // tt
    }
    __syncthreads();

    if (tid < 256) {
        int c = tid & 31, rg = tid >> 5;
        int r0 = rg * 4;
        float Srt[4], Stt[4];
        z_v7p(sm + OFF_SLOT + 1760 + r0 * 32 + c, Srt);
        z_v7p(sm + OFF_SLOT + 2976 + r0 * 32 + c, Stt);
        #pragma unroll
        for (int k = 0; k < 4; k++) {
            int r = r0 + k;
            float boxr = sm[OFF_BOXRR + r * 32 + c];
            float t1c = sm[OFF_RAWT + (r + 6) * 44 + (c + 6)];
            float zm1 = (Srt[k] * inv49) / sqrtf(boxr * (Stt[k] * inv49) + 1e-8f);
            if (t1c != 0.0f) { score += zm1; pix += 1.0f; }
        }
    }

    // ===== reduction + finalize =====
    #pragma unroll
    for (int off = 16; off; off >>= 1) {
        score += __shfl_down_sync(0xFFFFFFFFu, score, off);
        pix   += __shfl_down_sync(0xFFFFFFFFu, pix,   off);
    }
    if ((tid & 31) == 0) { redS[tid >> 5] = score; redP[tid >> 5] = pix; }
    __syncthreads();
    if (tid == 0) {
        float s = 0.0f, p = 0.0f;
        #pragma unroll
        for (int i = 0; i < 8; i++) { s += redS[i]; p += redP[i]; }
        atomicAdd(&g_score, (double)s);
        atomicAdd(&g_pixels, (double)p);
        __threadfence();
        unsigned int nblk = gridDim.x * gridDim.y;
        unsigned int t = atomicAdd(&g_ticket, 1u);
        if (t == nblk - 1u) {
            double ts = atomicAdd(&g_score, 0.0);
            double tp = atomicAdd(&g_pixels, 0.0);
            double mean = ts / fmax(tp, 1.0);
            out[0] = (tp > 0.0) ? (float)(0.5 * (1.0 - mean)) : 0.0f;
            g_score  = 0.0;
            g_pixels = 0.0;
            __threadfence();
            g_ticket = 0u;
        }
    }
}

// ---------------- launch ----------------
extern "C" void kernel_launch(void* const* d_in, const int* in_sizes, int n_in,
                              void* d_out, int out_size) {
    const float* focal   = (const float*)d_in[0];
    const float* aa      = (const float*)d_in[1];
    const float* centers = (const float*)d_in[2];
    const float* ref     = (const float*)d_in[3];
    const float* depth   = (const float*)d_in[4];
    const float* tgts    = (const float*)d_in[5];

    static int smem_set = 0;
    if (!smem_set) {
        cudaFuncSetAttribute(zncc2_kernel, cudaFuncAttributeMaxDynamicSharedMemorySize,
                             SMEM_FLOATS * (int)sizeof(float));
        smem_set = 1;
    }

    warp2_kernel<<<(NPIX / 2 + 255) / 256, 256>>>(depth, tgts, tgts + (size_t)NPIX,
                                                  focal, aa, centers);
    dim3 zg(W_IMG / 32, H_IMG / 32);
    zncc2_kernel<<<zg, ZBLK, SMEM_FLOATS * sizeof(float)>>>(ref, (float*)d_out);
}